// round 15
// baseline (speedup 1.0000x reference)
#include <cuda_runtime.h>
#include <math.h>

// Problem constants (fixed shapes for SagPooling_9852654977355)
#define NN   65536      // total nodes
#define DD   512        // feature dim
#define BG   64         // graphs
#define NPG  1024       // nodes per graph
#define DROPN 512       // lowest-rank nodes zeroed per graph

#define FIX_SCALE_F 16777216.0f        // 2^24 fixed-point scale (fp32)
#define INV_FIX_F   (1.0f / 16777216.0f)

#define DEG_BLOCKS   256               // 4 blocks per graph, smem-aggregated
#define DOT_BLOCKS   (NN / 8)          // 8 warps/block, 1 row/warp
#define FRONT_BLOCKS (DEG_BLOCKS + DOT_BLOCKS)
#define SCT_BLOCKS   256               // 4 blocks per graph

// Scratch (device globals — zero-initialized at load; re-zeroed by k_gate tail)
__device__ int      d_deg[NN];
__device__ unsigned d_agg[NN];         // 2^24 fixed-point accumulator
__device__ float    d_h[NN];           // raw F@w (normalization fused in scatter)
__device__ float    d_score[NN];
__device__ int      d_is64;

// ---------------------------------------------------------------------------
// Kernel 1 (fused front):
//   blocks [0, DEG_BLOCKS): in-degree, shared-mem aggregated per graph chunk
//   blocks [DEG_BLOCKS, FRONT_BLOCKS): raw dot h = F@w (bandwidth-bound)
// ---------------------------------------------------------------------------
__global__ void __launch_bounds__(256) k_front(const float* __restrict__ feat,
                                               const float* __restrict__ weight,
                                               const void* __restrict__ dst, int E) {
    __shared__ unsigned smem_u[NPG];   // deg bins OR (aliased) weight stage
    int tid = threadIdx.x;

    if (blockIdx.x < DEG_BLOCKS) {
        // ---- dtype probe (int64 ids have zero high words) ----
        __shared__ int s_is64;
        if (tid < 32) {
            unsigned hw = ((const unsigned*)dst)[2 * tid + 1];
            unsigned bad = __ballot_sync(0xffffffffu, hw != 0u);
            if (tid == 0) {
                s_is64 = (bad == 0u);
                if (blockIdx.x == 0) d_is64 = (bad == 0u);
            }
        }
        // zero bins
        for (int i = tid; i < NPG; i += 256) smem_u[i] = 0u;
        __syncthreads();
        int is64 = s_is64;

        int g     = blockIdx.x >> 2;           // graph id
        int chunk = blockIdx.x & 3;
        int epg   = E / BG;                    // edges per graph
        int cs    = (epg + 3) >> 2;
        int e0    = chunk * cs;
        int e1    = min(epg, e0 + cs);
        long long gbase = (long long)g * epg;
        int nbase = g * NPG;

        if (is64) {
            const long long* p = (const long long*)dst;
            for (int e = e0 + tid; e < e1; e += 256)
                atomicAdd(&smem_u[(int)p[gbase + e] - nbase], 1u);
        } else {
            const int* p = (const int*)dst;
            for (int e = e0 + tid; e < e1; e += 256)
                atomicAdd(&smem_u[p[gbase + e] - nbase], 1u);
        }
        __syncthreads();
        for (int i = tid; i < NPG; i += 256) {
            unsigned c = smem_u[i];
            if (c) atomicAdd(&d_deg[nbase + i], (int)c);
        }
    } else {
        // ---- raw dot: one warp per row, weight staged in shared ----
        float4* sw = (float4*)smem_u;          // 512 floats = 2KB, fits
        for (int i = tid; i < DD / 4; i += 256)
            sw[i] = ((const float4*)weight)[i];
        __syncthreads();

        int warp = tid >> 5;
        int lane = tid & 31;
        int row  = (blockIdx.x - DEG_BLOCKS) * 8 + warp;
        if (row >= NN) return;

        const float4* f = (const float4*)(feat + (long long)row * DD);
        float acc = 0.f;
        #pragma unroll
        for (int k = 0; k < 4; k++) {
            int j = lane + 32 * k;
            float4 a = f[j];
            float4 w = sw[j];
            acc += a.x * w.x + a.y * w.y + a.z * w.z + a.w * w.w;
        }
        #pragma unroll
        for (int o = 16; o > 0; o >>= 1)
            acc += __shfl_xor_sync(0xffffffffu, acc, o);
        if (lane == 0) d_h[row] = acc;
    }
}

// ---------------------------------------------------------------------------
// Kernel 2: agg[dst] += h[src] * deg[src]^-0.5, shared-mem aggregated.
// Normalization fused per-edge (identical fp32 computation per edge ->
// order-independent integer bins -> bit-deterministic).
// ---------------------------------------------------------------------------
__global__ void __launch_bounds__(256) k_scatter(const void* __restrict__ src,
                                                 const void* __restrict__ dst, int E) {
    __shared__ unsigned bins[NPG];
    int tid = threadIdx.x;
    int is64 = d_is64;

    for (int i = tid; i < NPG; i += 256) bins[i] = 0u;
    __syncthreads();

    int g     = blockIdx.x >> 2;
    int chunk = blockIdx.x & 3;
    int epg   = E / BG;
    int cs    = (epg + 3) >> 2;
    int e0    = chunk * cs;
    int e1    = min(epg, e0 + cs);
    long long gbase = (long long)g * epg;
    int nbase = g * NPG;

    if (is64) {
        const long long* ps = (const long long*)src;
        const long long* pd = (const long long*)dst;
        for (int e = e0 + tid; e < e1; e += 256) {
            int s = (int)ps[gbase + e];
            int d = (int)pd[gbase + e];
            int dg = d_deg[s];
            float nrm = dg > 0 ? rsqrtf((float)dg) : 0.f;
            int q = (int)(d_h[s] * nrm * FIX_SCALE_F);
            atomicAdd(&bins[d - nbase], (unsigned)q);
        }
    } else {
        const int* ps = (const int*)src;
        const int* pd = (const int*)dst;
        for (int e = e0 + tid; e < e1; e += 256) {
            int s = ps[gbase + e];
            int d = pd[gbase + e];
            int dg = d_deg[s];
            float nrm = dg > 0 ? rsqrtf((float)dg) : 0.f;
            int q = (int)(d_h[s] * nrm * FIX_SCALE_F);
            atomicAdd(&bins[d - nbase], (unsigned)q);
        }
    }
    __syncthreads();
    for (int i = tid; i < NPG; i += 256) {
        unsigned c = bins[i];
        if (c) atomicAdd(&d_agg[nbase + i], c);
    }
}

// ---------------------------------------------------------------------------
// Kernel 3: score + per-graph EXACT rank mask via 8-bit radix select.
// 256 threads x 4 nodes each: 8 warps -> barriers ~4x cheaper than 32-warp
// version, more ILP per thread. Plain shared atomics (conflict theory was
// falsified in R8). Warp-0 parallel bucket select. Stable-argsort ties.
// ---------------------------------------------------------------------------
__global__ void __launch_bounds__(256) k_rank(const float* __restrict__ bias) {
    __shared__ unsigned skey[NPG];
    __shared__ unsigned hist[256];
    __shared__ unsigned s_sel;
    __shared__ unsigned s_less;
    __shared__ unsigned s_rank;

    int t = threadIdx.x;
    int base = blockIdx.x * NPG;
    float b0 = bias[0];

    float    sc[4];
    unsigned key[4];
    #pragma unroll
    for (int i = 0; i < 4; i++) {
        int idx  = t + 256 * i;          // coalesced
        int node = base + idx;
        int q  = (int)d_agg[node];
        int dg = d_deg[node];
        float nrm = dg > 0 ? rsqrtf((float)dg) : 0.f;
        float s = (float)q * INV_FIX_F * nrm + b0;
        s = s > 0.f ? s : 0.f;
        sc[i]  = s;
        key[i] = __float_as_uint(s);     // s >= 0 -> monotone uint ordering
        skey[idx] = key[i];
    }
    if (t == 0) { s_less = 0u; s_rank = DROPN - 1; }

    unsigned prefix = 0u;
    unsigned act = 0xFu;                 // per-key active flags

    #pragma unroll
    for (int shift = 24; shift >= 0; shift -= 8) {
        hist[t] = 0u;
        __syncthreads();
        #pragma unroll
        for (int i = 0; i < 4; i++)
            if (act & (1u << i))
                atomicAdd(&hist[(key[i] >> shift) & 255u], 1u);
        __syncthreads();
        if (t < 32) {
            // each lane owns 8 bins
            unsigned loc[8];
            unsigned s = 0u;
            #pragma unroll
            for (int i = 0; i < 8; i++) { loc[i] = hist[t * 8 + i]; s += loc[i]; }
            // inclusive warp scan of lane sums
            unsigned p = s;
            #pragma unroll
            for (int o = 1; o < 32; o <<= 1) {
                unsigned n = __shfl_up_sync(0xffffffffu, p, o);
                if (t >= o) p += n;
            }
            unsigned excl = p - s;
            unsigned r = s_rank;             // all lanes read before any store
            if (r >= excl && r < p) {        // crossing lies in this lane's bins
                unsigned cum = excl;
                int b = 0;
                #pragma unroll
                for (int i = 0; i < 8; i++) {
                    if (cum + loc[i] > r) { b = i; break; }
                    cum += loc[i];
                }
                s_sel  = (unsigned)(t * 8 + b);
                s_less += cum;
                s_rank = r - cum;
            }
        }
        __syncthreads();
        unsigned sel = s_sel;
        #pragma unroll
        for (int i = 0; i < 4; i++)
            if ((act & (1u << i)) && ((key[i] >> shift) & 255u) != sel)
                act &= ~(1u << i);
        prefix |= sel << shift;
    }

    unsigned T = prefix;     // threshold key (stable rank DROPN-1)
    unsigned L = s_less;     // # keys strictly < T

    #pragma unroll
    for (int i = 0; i < 4; i++) {
        int idx = t + 256 * i;
        float out;
        if (key[i] > T) {
            out = sc[i];
        } else if (key[i] == T && T != 0u) {
            // stable tie: among equals, lower index takes lower rank
            int c = 0;
            for (int j = 0; j < idx; j++) c += (skey[j] == T);
            out = ((int)L + c >= DROPN) ? sc[i] : 0.f;
        } else {
            out = 0.f;       // dropped (or zero score: gates to 0 either way)
        }
        d_score[base + idx] = out;
    }
}

// ---------------------------------------------------------------------------
// Kernel 4: out = features * score (skip feature read for zeroed rows),
// then re-zero deg/agg for the next graph replay.
// ---------------------------------------------------------------------------
__global__ void __launch_bounds__(256) k_gate(const float* __restrict__ feat,
                                              float* __restrict__ out) {
    int warp = threadIdx.x >> 5;
    int lane = threadIdx.x & 31;
    int row  = blockIdx.x * 8 + warp;
    if (row < NN) {
        float s = d_score[row];
        const float4* fi = (const float4*)(feat + (long long)row * DD);
        float4*       fo = (float4*)(out + (long long)row * DD);
        if (s == 0.f) {
            float4 z = make_float4(0.f, 0.f, 0.f, 0.f);
            #pragma unroll
            for (int k = 0; k < 4; k++) fo[lane + 32 * k] = z;
        } else {
            #pragma unroll
            for (int k = 0; k < 4; k++) {
                int j = lane + 32 * k;
                float4 a = fi[j];
                a.x *= s; a.y *= s; a.z *= s; a.w *= s;
                fo[j] = a;
            }
        }
    }
    // re-zero scratch for next replay
    int gid = blockIdx.x * blockDim.x + threadIdx.x;
    if (gid < NN) { d_deg[gid] = 0; d_agg[gid] = 0u; }
}

// ---------------------------------------------------------------------------
extern "C" void kernel_launch(void* const* d_in, const int* in_sizes, int n_in,
                              void* d_out, int out_size) {
    const float* feat   = (const float*)d_in[0];
    const void*  src    = d_in[1];
    const void*  dst    = d_in[2];
    const float* weight = (const float*)d_in[3];
    const float* bias   = (const float*)d_in[4];
    float* out = (float*)d_out;
    int E = in_sizes[1];

    k_front<<<FRONT_BLOCKS, 256>>>(feat, weight, dst, E);
    k_scatter<<<SCT_BLOCKS, 256>>>(src, dst, E);
    k_rank<<<BG, 256>>>(bias);
    k_gate<<<NN / 8, 256>>>(feat, out);
}

// round 16
// speedup vs baseline: 1.0189x; 1.0189x over previous
#include <cuda_runtime.h>
#include <math.h>

// Problem constants (fixed shapes for SagPooling_9852654977355)
#define NN   65536      // total nodes
#define DD   512        // feature dim
#define BG   64         // graphs
#define NPG  1024       // nodes per graph
#define DROPN 512       // lowest-rank nodes zeroed per graph

#define FIX_SCALE_F 16777216.0f        // 2^24 fixed-point scale (fp32)
#define INV_FIX_F   (1.0f / 16777216.0f)

#define DEG_BLOCKS   256               // 4 blocks per graph, smem-aggregated
#define DOT_BLOCKS   (NN / 8)          // 8 warps/block, 1 row/warp
#define FRONT_BLOCKS (DEG_BLOCKS + DOT_BLOCKS)
#define SCT_BLOCKS   256               // 4 blocks per graph

// Scratch (device globals — zero-initialized at load; re-zeroed by k_gate tail;
// d_cnt self-resets via atomicInc mod 4)
__device__ int      d_deg[NN];
__device__ unsigned d_agg[NN];         // 2^24 fixed-point accumulator
__device__ float    d_h[NN];           // raw F@w (normalization fused in scatter)
__device__ float    d_score[NN];
__device__ unsigned d_cnt[BG];         // per-graph scatter-done counter
__device__ int      d_is64;

// ---------------------------------------------------------------------------
// Kernel 1 (fused front):
//   blocks [0, DEG_BLOCKS): in-degree, shared-mem aggregated per graph chunk
//   blocks [DEG_BLOCKS, FRONT_BLOCKS): raw dot h = F@w (bandwidth-bound)
// ---------------------------------------------------------------------------
__global__ void __launch_bounds__(256) k_front(const float* __restrict__ feat,
                                               const float* __restrict__ weight,
                                               const void* __restrict__ dst, int E) {
    __shared__ unsigned smem_u[NPG];   // deg bins OR (aliased) weight stage
    int tid = threadIdx.x;

    if (blockIdx.x < DEG_BLOCKS) {
        // ---- dtype probe (int64 ids have zero high words) ----
        __shared__ int s_is64;
        if (tid < 32) {
            unsigned hw = ((const unsigned*)dst)[2 * tid + 1];
            unsigned bad = __ballot_sync(0xffffffffu, hw != 0u);
            if (tid == 0) {
                s_is64 = (bad == 0u);
                if (blockIdx.x == 0) d_is64 = (bad == 0u);
            }
        }
        // zero bins
        for (int i = tid; i < NPG; i += 256) smem_u[i] = 0u;
        __syncthreads();
        int is64 = s_is64;

        int g     = blockIdx.x >> 2;           // graph id
        int chunk = blockIdx.x & 3;
        int epg   = E / BG;                    // edges per graph
        int cs    = (epg + 3) >> 2;
        int e0    = chunk * cs;
        int e1    = min(epg, e0 + cs);
        long long gbase = (long long)g * epg;
        int nbase = g * NPG;

        if (is64) {
            const long long* p = (const long long*)dst;
            for (int e = e0 + tid; e < e1; e += 256)
                atomicAdd(&smem_u[(int)p[gbase + e] - nbase], 1u);
        } else {
            const int* p = (const int*)dst;
            for (int e = e0 + tid; e < e1; e += 256)
                atomicAdd(&smem_u[p[gbase + e] - nbase], 1u);
        }
        __syncthreads();
        for (int i = tid; i < NPG; i += 256) {
            unsigned c = smem_u[i];
            if (c) atomicAdd(&d_deg[nbase + i], (int)c);
        }
    } else {
        // ---- raw dot: one warp per row, weight staged in shared ----
        float4* sw = (float4*)smem_u;          // 512 floats = 2KB, fits
        for (int i = tid; i < DD / 4; i += 256)
            sw[i] = ((const float4*)weight)[i];
        __syncthreads();

        int warp = tid >> 5;
        int lane = tid & 31;
        int row  = (blockIdx.x - DEG_BLOCKS) * 8 + warp;
        if (row >= NN) return;

        const float4* f = (const float4*)(feat + (long long)row * DD);
        float acc = 0.f;
        #pragma unroll
        for (int k = 0; k < 4; k++) {
            int j = lane + 32 * k;
            float4 a = f[j];
            float4 w = sw[j];
            acc += a.x * w.x + a.y * w.y + a.z * w.z + a.w * w.w;
        }
        #pragma unroll
        for (int o = 16; o > 0; o >>= 1)
            acc += __shfl_xor_sync(0xffffffffu, acc, o);
        if (lane == 0) d_h[row] = acc;
    }
}

// ---------------------------------------------------------------------------
// Kernel 2 (fused scatter + rank):
// Phase A: agg[dst] += h[src] * deg[src]^-0.5, shared-mem aggregated,
//          integer bins (order-independent -> bit-deterministic).
// Phase B: the LAST of each graph's 4 blocks (atomicInc handoff; counter
//          self-resets mod 4 each replay) runs the graph's exact radix-select
//          rank mask inline, overlapping with other graphs' scatter.
// ---------------------------------------------------------------------------
__global__ void __launch_bounds__(256) k_scatter_rank(const void* __restrict__ src,
                                                      const void* __restrict__ dst,
                                                      const float* __restrict__ bias,
                                                      int E) {
    __shared__ unsigned bins[NPG];
    __shared__ unsigned skey[NPG];
    __shared__ unsigned hist[256];
    __shared__ unsigned s_sel;
    __shared__ unsigned s_less;
    __shared__ unsigned s_rank;
    __shared__ unsigned s_old;

    int tid = threadIdx.x;
    int is64 = d_is64;

    for (int i = tid; i < NPG; i += 256) bins[i] = 0u;
    __syncthreads();

    int g     = blockIdx.x >> 2;
    int chunk = blockIdx.x & 3;
    int epg   = E / BG;
    int cs    = (epg + 3) >> 2;
    int e0    = chunk * cs;
    int e1    = min(epg, e0 + cs);
    long long gbase = (long long)g * epg;
    int nbase = g * NPG;

    if (is64) {
        const long long* ps = (const long long*)src;
        const long long* pd = (const long long*)dst;
        for (int e = e0 + tid; e < e1; e += 256) {
            int s = (int)ps[gbase + e];
            int d = (int)pd[gbase + e];
            int dg = d_deg[s];
            float nrm = dg > 0 ? rsqrtf((float)dg) : 0.f;
            int q = (int)(d_h[s] * nrm * FIX_SCALE_F);
            atomicAdd(&bins[d - nbase], (unsigned)q);
        }
    } else {
        const int* ps = (const int*)src;
        const int* pd = (const int*)dst;
        for (int e = e0 + tid; e < e1; e += 256) {
            int s = ps[gbase + e];
            int d = pd[gbase + e];
            int dg = d_deg[s];
            float nrm = dg > 0 ? rsqrtf((float)dg) : 0.f;
            int q = (int)(d_h[s] * nrm * FIX_SCALE_F);
            atomicAdd(&bins[d - nbase], (unsigned)q);
        }
    }
    __syncthreads();
    for (int i = tid; i < NPG; i += 256) {
        unsigned c = bins[i];
        if (c) atomicAdd(&d_agg[nbase + i], c);
    }

    // ---- handoff: last of this graph's 4 blocks runs the rank ----
    __threadfence();
    if (tid == 0) s_old = atomicInc(&d_cnt[g], 3u);   // returns to 0 after 4th
    __syncthreads();
    if (s_old != 3u) return;
    __threadfence();   // see all 4 blocks' d_agg atomics

    // ---- rank: exact 8-bit radix select, 4 nodes/thread ----
    int base = nbase;
    float b0 = bias[0];

    float    sc[4];
    unsigned key[4];
    #pragma unroll
    for (int i = 0; i < 4; i++) {
        int idx  = tid + 256 * i;        // coalesced
        int node = base + idx;
        int q  = (int)d_agg[node];
        int dg = d_deg[node];
        float nrm = dg > 0 ? rsqrtf((float)dg) : 0.f;
        float s = (float)q * INV_FIX_F * nrm + b0;
        s = s > 0.f ? s : 0.f;
        sc[i]  = s;
        key[i] = __float_as_uint(s);     // s >= 0 -> monotone uint ordering
        skey[idx] = key[i];
    }
    if (tid == 0) { s_less = 0u; s_rank = DROPN - 1; }

    unsigned prefix = 0u;
    unsigned act = 0xFu;                 // per-key active flags

    #pragma unroll
    for (int shift = 24; shift >= 0; shift -= 8) {
        hist[tid] = 0u;
        __syncthreads();
        #pragma unroll
        for (int i = 0; i < 4; i++)
            if (act & (1u << i))
                atomicAdd(&hist[(key[i] >> shift) & 255u], 1u);
        __syncthreads();
        if (tid < 32) {
            // each lane owns 8 bins
            unsigned loc[8];
            unsigned s = 0u;
            #pragma unroll
            for (int i = 0; i < 8; i++) { loc[i] = hist[tid * 8 + i]; s += loc[i]; }
            // inclusive warp scan of lane sums
            unsigned p = s;
            #pragma unroll
            for (int o = 1; o < 32; o <<= 1) {
                unsigned n = __shfl_up_sync(0xffffffffu, p, o);
                if (tid >= o) p += n;
            }
            unsigned excl = p - s;
            unsigned r = s_rank;             // all lanes read before any store
            if (r >= excl && r < p) {        // crossing lies in this lane's bins
                unsigned cum = excl;
                int b = 0;
                #pragma unroll
                for (int i = 0; i < 8; i++) {
                    if (cum + loc[i] > r) { b = i; break; }
                    cum += loc[i];
                }
                s_sel  = (unsigned)(tid * 8 + b);
                s_less += cum;
                s_rank = r - cum;
            }
        }
        __syncthreads();
        unsigned sel = s_sel;
        #pragma unroll
        for (int i = 0; i < 4; i++)
            if ((act & (1u << i)) && ((key[i] >> shift) & 255u) != sel)
                act &= ~(1u << i);
        prefix |= sel << shift;
    }

    unsigned T = prefix;     // threshold key (stable rank DROPN-1)
    unsigned L = s_less;     // # keys strictly < T

    #pragma unroll
    for (int i = 0; i < 4; i++) {
        int idx = tid + 256 * i;
        float out;
        if (key[i] > T) {
            out = sc[i];
        } else if (key[i] == T && T != 0u) {
            // stable tie: among equals, lower index takes lower rank
            int c = 0;
            for (int j = 0; j < idx; j++) c += (skey[j] == T);
            out = ((int)L + c >= DROPN) ? sc[i] : 0.f;
        } else {
            out = 0.f;       // dropped (or zero score: gates to 0 either way)
        }
        d_score[base + idx] = out;
    }
}

// ---------------------------------------------------------------------------
// Kernel 3: out = features * score (skip feature read for zeroed rows),
// then re-zero deg/agg for the next graph replay.
// ---------------------------------------------------------------------------
__global__ void __launch_bounds__(256) k_gate(const float* __restrict__ feat,
                                              float* __restrict__ out) {
    int warp = threadIdx.x >> 5;
    int lane = threadIdx.x & 31;
    int row  = blockIdx.x * 8 + warp;
    if (row < NN) {
        float s = d_score[row];
        const float4* fi = (const float4*)(feat + (long long)row * DD);
        float4*       fo = (float4*)(out + (long long)row * DD);
        if (s == 0.f) {
            float4 z = make_float4(0.f, 0.f, 0.f, 0.f);
            #pragma unroll
            for (int k = 0; k < 4; k++) fo[lane + 32 * k] = z;
        } else {
            #pragma unroll
            for (int k = 0; k < 4; k++) {
                int j = lane + 32 * k;
                float4 a = fi[j];
                a.x *= s; a.y *= s; a.z *= s; a.w *= s;
                fo[j] = a;
            }
        }
    }
    // re-zero scratch for next replay
    int gid = blockIdx.x * blockDim.x + threadIdx.x;
    if (gid < NN) { d_deg[gid] = 0; d_agg[gid] = 0u; }
}

// ---------------------------------------------------------------------------
extern "C" void kernel_launch(void* const* d_in, const int* in_sizes, int n_in,
                              void* d_out, int out_size) {
    const float* feat   = (const float*)d_in[0];
    const void*  src    = d_in[1];
    const void*  dst    = d_in[2];
    const float* weight = (const float*)d_in[3];
    const float* bias   = (const float*)d_in[4];
    float* out = (float*)d_out;
    int E = in_sizes[1];

    k_front<<<FRONT_BLOCKS, 256>>>(feat, weight, dst, E);
    k_scatter_rank<<<SCT_BLOCKS, 256>>>(src, dst, bias, E);
    k_gate<<<NN / 8, 256>>>(feat, out);
}